// round 17
// baseline (speedup 1.0000x reference)
#include <cuda_runtime.h>
#include <cuda_bf16.h>
#include <math.h>
#include <mma.h>

using namespace nvcuda;

// Problem constants
#define B 4
#define T 512
#define C 256
#define C2 512
#define HEADS 4
#define MAXOFF 2
#define M (B * T)      // 2048

#define TI 32          // i-tile per block (rep)
#define TJ 64          // j-tile per block (rep)
#define NJT (T / TJ)   // 8 j-tiles
#define CK 128         // c chunk (rep)

typedef unsigned long long u64;

// Scratch (allocation-free: device globals)
__device__ float g_subj[M * C];
__device__ float g_obj[M * C];
__device__ float g_part[M * NJT * HEADS];       // partial exp-sums per j-tile
__device__ float g_swow[2 * M * HEADS];         // Sw rows 0..M-1, Ow rows M..

// packed f32x2 helpers
static __device__ __forceinline__ u64 fma2(u64 a, u64 b, u64 c) {
    u64 r; asm("fma.rn.f32x2 %0, %1, %2, %3;" : "=l"(r) : "l"(a), "l"(b), "l"(c)); return r;
}
static __device__ __forceinline__ float2 unpack2(u64 v) {
    float2 r; asm("mov.b64 {%0, %1}, %2;" : "=f"(r.x), "=f"(r.y) : "l"(v)); return r;
}
// packed min (FMNMX on ALU pipe); union form lets ptxas pair-allocate
static __device__ __forceinline__ u64 fmin2(u64 a, u64 b) {
    union { u64 v; float2 f; } ua, ub, uc;
    ua.v = a; ub.v = b;
    uc.f.x = fminf(ua.f.x, ub.f.x);
    uc.f.y = fminf(ua.f.y, ub.f.y);
    return uc.v;
}

// ---------------------------------------------------------------------------
// Kernel 1: max-pool along channel (window 5, pad 2) + concat -> x_new
// ---------------------------------------------------------------------------
__global__ void pool_concat_kernel(const float* __restrict__ x,
                                   float* __restrict__ xnew) {
    int idx = blockIdx.x * 256 + threadIdx.x;
    if (idx >= M * C2) return;
    int cc = idx & (C2 - 1);
    int bt = idx >> 9;
    const float* xr = x + bt * C;
    float v;
    if (cc < C) {
        int lo = cc - MAXOFF; if (lo < 0) lo = 0;
        int hi = cc + MAXOFF; if (hi > C - 1) hi = C - 1;
        v = -INFINITY;
        #pragma unroll 5
        for (int c = lo; c <= hi; c++) v = fmaxf(v, xr[c]);
    } else {
        v = xr[cc - C];
    }
    xnew[idx] = v;
}

// ---------------------------------------------------------------------------
// Kernel 2: projection GEMMs on the TENSOR pipe (tf32 wmma, m16n16k8).
// Block tile 64m x 64n, 256 threads = 8 warps (4m x 2n); warp tile 16m x 32n.
// ---------------------------------------------------------------------------
__global__ void __launch_bounds__(256)
gemm_kernel(const float* __restrict__ A,
            const float* __restrict__ W0,
            const float* __restrict__ b0,
            const float* __restrict__ W1,
            const float* __restrict__ b1,
            float* __restrict__ out0,
            float* __restrict__ out1) {
    __shared__ float As[64 * 36];   // [m][k], stride 36
    __shared__ float Ws[32 * 68];   // [k][n], stride 68
    __shared__ float Cs[64 * 68];   // epilogue staging [m][n], stride 68

    const float* W    = blockIdx.z ? W1 : W0;
    const float* bias = blockIdx.z ? b1 : b0;
    float* out        = blockIdx.z ? out1 : out0;

    const int tid = threadIdx.x;
    const int warp = tid >> 5;
    const int wm = warp >> 1;
    const int wn = warp & 1;
    const int bm = blockIdx.y * 64;
    const int bn = blockIdx.x * 64;

    wmma::fragment<wmma::accumulator, 16, 16, 8, float> c0, c1;
    wmma::fill_fragment(c0, 0.0f);
    wmma::fill_fragment(c1, 0.0f);

    for (int k0 = 0; k0 < C2; k0 += 32) {
        #pragma unroll
        for (int l = 0; l < 2; l++) {
            int t = tid + l * 256;
            int m = t >> 3, kq = t & 7;
            float4 v = *(const float4*)&A[(size_t)(bm + m) * C2 + k0 + 4 * kq];
            *(float4*)&As[m * 36 + 4 * kq] = v;
        }
        #pragma unroll
        for (int l = 0; l < 2; l++) {
            int t = tid + l * 256;
            int kw = t >> 4, nq = t & 15;
            float4 v = *(const float4*)&W[(size_t)(k0 + kw) * C + bn + 4 * nq];
            *(float4*)&Ws[kw * 68 + 4 * nq] = v;
        }
        __syncthreads();

        #pragma unroll
        for (int ks = 0; ks < 4; ks++) {
            wmma::fragment<wmma::matrix_a, 16, 16, 8, wmma::precision::tf32,
                           wmma::row_major> a;
            wmma::load_matrix_sync(a, &As[(wm * 16) * 36 + ks * 8], 36);
            #pragma unroll
            for (int i = 0; i < a.num_elements; i++)
                a.x[i] = wmma::__float_to_tf32(a.x[i]);

            wmma::fragment<wmma::matrix_b, 16, 16, 8, wmma::precision::tf32,
                           wmma::row_major> bfr;
            wmma::load_matrix_sync(bfr, &Ws[(ks * 8) * 68 + wn * 32], 68);
            #pragma unroll
            for (int i = 0; i < bfr.num_elements; i++)
                bfr.x[i] = wmma::__float_to_tf32(bfr.x[i]);
            wmma::mma_sync(c0, a, bfr, c0);

            wmma::load_matrix_sync(bfr, &Ws[(ks * 8) * 68 + wn * 32 + 16], 68);
            #pragma unroll
            for (int i = 0; i < bfr.num_elements; i++)
                bfr.x[i] = wmma::__float_to_tf32(bfr.x[i]);
            wmma::mma_sync(c1, a, bfr, c1);
        }
        __syncthreads();
    }

    wmma::store_matrix_sync(&Cs[(wm * 16) * 68 + wn * 32], c0, 68,
                            wmma::mem_row_major);
    wmma::store_matrix_sync(&Cs[(wm * 16) * 68 + wn * 32 + 16], c1, 68,
                            wmma::mem_row_major);
    __syncthreads();

    #pragma unroll
    for (int l = 0; l < 4; l++) {
        int t = tid + l * 256;
        int m = t >> 4, nq = t & 15;
        float4 v = *(const float4*)&Cs[m * 68 + 4 * nq];
        float4 bv = *(const float4*)&bias[bn + 4 * nq];
        v.x += bv.x; v.y += bv.y; v.z += bv.z; v.w += bv.w;
        *(float4*)&out[(size_t)(bm + m) * C + bn + 4 * nq] = v;
    }
}

// ---------------------------------------------------------------------------
// Kernel 2b: Sw[j,h] = subj[j,:] @ W_t  and  Ow[i,h] = obj[i,:] @ W_t.
// ---------------------------------------------------------------------------
__global__ void __launch_bounds__(128)
swow_kernel(const float* __restrict__ subj,
            const float* __restrict__ obj,
            const float* __restrict__ W_t,
            float* __restrict__ swow) {
    int gw = (blockIdx.x * 128 + threadIdx.x) >> 5;   // 0..4095
    int lane = threadIdx.x & 31;
    const float* src = (gw < M) ? subj : obj;
    int row = gw & (M - 1);

    float4 a = make_float4(0.f, 0.f, 0.f, 0.f);
    const float4* wt4 = (const float4*)W_t;
    #pragma unroll
    for (int c = lane; c < C; c += 32) {
        float s = src[row * C + c];
        float4 w = wt4[c];
        a.x += s * w.x; a.y += s * w.y; a.z += s * w.z; a.w += s * w.w;
    }
    #pragma unroll
    for (int m = 16; m >= 1; m >>= 1) {
        a.x += __shfl_xor_sync(0xffffffffu, a.x, m);
        a.y += __shfl_xor_sync(0xffffffffu, a.y, m);
        a.z += __shfl_xor_sync(0xffffffffu, a.z, m);
        a.w += __shfl_xor_sync(0xffffffffu, a.w, m);
    }
    if (lane == 0) ((float4*)swow)[gw] = a;
}

// ---------------------------------------------------------------------------
// Kernel 3a: rep = Sw[j]+Ow[i]+b - 2*sum_c min(s,o)*w.   HEADS-SPLIT version:
// 256 threads = 16 tx (j, stride-16) x 8 ty (i, stride-8) x 2 th (head pair).
// Each thread: 4i x 4j x 2h -> acc 32 u64 = 64 regs.  Tile/loader/swizzle
// identical to the verified R7 shape.
// ---------------------------------------------------------------------------
__global__ void __launch_bounds__(256, 2)
rep_exp_kernel(const float* __restrict__ subj,
               const float* __restrict__ obj,
               const float* __restrict__ W_t,
               const float* __restrict__ b_t,
               const float* __restrict__ swow,
               float* __restrict__ attn,
               float* __restrict__ part) {
    __shared__ float s_sh[TJ * CK];     // [jrow][c], swizzled (32KB)
    __shared__ float o_sh[TI * CK];     // [irow][c], swizzled (16KB)
    __shared__ float w_sh[HEADS * C];   // [h][c] = -2*W_t (4KB)

    const int tid = threadIdx.x;
    const int tx = tid & 15;           // j: j0 + tx + 16q
    const int ty = (tid >> 4) & 7;     // i: i0 + ty + 8p
    const int th = tid >> 7;           // head pair: h = 2*th, 2*th+1
    const int jt = blockIdx.x;
    const int j0 = jt * TJ;
    const int i0 = blockIdx.y * TI;
    const int b  = blockIdx.z;

    // w_sh[h][c] = -2 * W_t[c*4+h]  (one c per thread)
    {
        int c = tid;
        float4 wv = *(const float4*)&W_t[c * 4];
        w_sh[0 * C + c] = -2.0f * wv.x;
        w_sh[1 * C + c] = -2.0f * wv.y;
        w_sh[2 * C + c] = -2.0f * wv.z;
        w_sh[3 * C + c] = -2.0f * wv.w;
    }

    u64 acc[4][4][2];
    #pragma unroll
    for (int p = 0; p < 4; p++)
        #pragma unroll
        for (int q = 0; q < 4; q++) {
            acc[p][q][0] = 0ULL;
            acc[p][q][1] = 0ULL;
        }

    const int swj = tx & 7;
    const float* sp[4];
    const float* op[4];
    #pragma unroll
    for (int q = 0; q < 4; q++) sp[q] = s_sh + (tx + 16 * q) * CK;
    #pragma unroll
    for (int p = 0; p < 4; p++) op[p] = o_sh + (ty + 8 * p) * CK;

    for (int ck = 0; ck < C / CK; ck++) {
        const int cbase = ck * CK;
        // s: 64 rows x 128 c  (2048 float4, 256 threads -> l<8)
        #pragma unroll
        for (int l = 0; l < 8; l++) {
            int t = tid + l * 256;
            int row = t >> 5;          // 0..63
            int ccg = t & 31;
            int phys = (ccg ^ (row & 7)) << 2;
            float4 sv = *(const float4*)&subj[(b * T + j0 + row) * C + cbase + ccg * 4];
            *(float4*)&s_sh[row * CK + phys] = sv;
        }
        // o: 32 rows x 128 c  (1024 float4 -> l<4)
        #pragma unroll
        for (int l = 0; l < 4; l++) {
            int t = tid + l * 256;
            int row = t >> 5;          // 0..31
            int ccg = t & 31;
            int phys = (ccg ^ (row & 7)) << 2;
            float4 ov = *(const float4*)&obj[(b * T + i0 + row) * C + cbase + ccg * 4];
            *(float4*)&o_sh[row * CK + phys] = ov;
        }
        __syncthreads();

        const float* wpA = w_sh + (2 * th + 0) * C + cbase;
        const float* wpB = w_sh + (2 * th + 1) * C + cbase;

        #pragma unroll 1
        for (int g = 0; g < CK / 4; g++) {
            const int gs = ((g ^ swj) << 2);
            const int gi = ((g ^ ty) << 2);
            ulonglong2 S[4], P[4], WA, WB;
            #pragma unroll
            for (int q = 0; q < 4; q++) S[q] = *(const ulonglong2*)(sp[q] + gs);
            #pragma unroll
            for (int p = 0; p < 4; p++) P[p] = *(const ulonglong2*)(op[p] + gi);
            WA = *(const ulonglong2*)(wpA + g * 4);
            WB = *(const ulonglong2*)(wpB + g * 4);

            #pragma unroll
            for (int p = 0; p < 4; p++) {
                #pragma unroll
                for (int q = 0; q < 4; q++) {
                    u64 m0 = fmin2(S[q].x, P[p].x);
                    acc[p][q][0] = fma2(m0, WA.x, acc[p][q][0]);
                    acc[p][q][1] = fma2(m0, WB.x, acc[p][q][1]);
                    u64 m1 = fmin2(S[q].y, P[p].y);
                    acc[p][q][0] = fma2(m1, WA.y, acc[p][q][0]);
                    acc[p][q][1] = fma2(m1, WB.y, acc[p][q][1]);
                }
            }
        }
        __syncthreads();
    }

    // Epilogue: z = relu(Sw[j] + Ow[i] + b + acc) for heads 2th, 2th+1
    const float2 btv = *(const float2*)&b_t[2 * th];
    const float* swbase = swow;                // [row][4]
    const float* owbase = swow + (size_t)M * HEADS;

    float2 owv[4];
    #pragma unroll
    for (int p = 0; p < 4; p++)
        owv[p] = *(const float2*)&owbase[(b * T + i0 + ty + 8 * p) * HEADS + 2 * th];

    #pragma unroll
    for (int p = 0; p < 4; p++) {
        int i = i0 + ty + 8 * p;
        float2 ps = make_float2(0.f, 0.f);
        float base_x = owv[p].x + btv.x;
        float base_y = owv[p].y + btv.y;
        #pragma unroll
        for (int q = 0; q < 4; q++) {
            int j = j0 + tx + 16 * q;
            float2 swv = *(const float2*)&swbase[(b * T + j) * HEADS + 2 * th];
            float2 f0 = unpack2(acc[p][q][0]);
            float2 f1 = unpack2(acc[p][q][1]);
            float2 ev;
            ev.x = __expf(fmaxf(f0.x + f0.y + swv.x + base_x, 0.0f));
            ev.y = __expf(fmaxf(f1.x + f1.y + swv.y + base_y, 0.0f));
            *(float2*)&attn[(((size_t)(b * T + i)) * T + j) * HEADS + 2 * th] = ev;
            ps.x += ev.x; ps.y += ev.y;
        }
        #pragma unroll
        for (int m = 8; m >= 1; m >>= 1) {
            ps.x += __shfl_xor_sync(0xffffffffu, ps.x, m);
            ps.y += __shfl_xor_sync(0xffffffffu, ps.y, m);
        }
        if (tx == 0)
            *(float2*)&part[((size_t)(b * T + i) * NJT + jt) * HEADS + 2 * th] = ps;
    }
}

// ---------------------------------------------------------------------------
// Kernel 3b: denominator + normalize + mask; 2 rows per block (shared mask j).
// ---------------------------------------------------------------------------
__global__ void __launch_bounds__(256)
normalize_kernel(const float* __restrict__ part,
                 const int* __restrict__ mask,
                 float* __restrict__ attn) {
    __shared__ float sinv[8];
    const int r = blockIdx.x;          // rows 2r, 2r+1
    const int tid = threadIdx.x;
    const int lane = tid & 31;
    const int wid = tid >> 5;

    if (wid < 2) {
        int row = 2 * r + wid;
        float v = part[row * (NJT * HEADS) + lane];
        v += __shfl_xor_sync(0xffffffffu, v, 4);
        v += __shfl_xor_sync(0xffffffffu, v, 8);
        v += __shfl_xor_sync(0xffffffffu, v, 16);
        if (lane < 4) sinv[wid * 4 + lane] = 1.0f / v;
    }
    __syncthreads();

    const float4 iv0 = make_float4(sinv[0], sinv[1], sinv[2], sinv[3]);
    const float4 iv1 = make_float4(sinv[4], sinv[5], sinv[6], sinv[7]);
    const int bi0 = 2 * r;
    const int b = bi0 >> 9;
    const int mi0 = mask[bi0];
    const int mi1 = mask[bi0 + 1];
    float4* arow0 = (float4*)attn + (size_t)bi0 * T;
    float4* arow1 = arow0 + T;

    #pragma unroll
    for (int rr = 0; rr < 2; rr++) {
        int j = tid + rr * 256;
        int mj = mask[b * T + j];
        float k0 = (mi0 && mj) ? 0.0f : 1.0f;
        float k1 = (mi1 && mj) ? 0.0f : 1.0f;
        float4 v0 = arow0[j];
        float4 v1 = arow1[j];
        v0.x *= iv0.x * k0; v0.y *= iv0.y * k0; v0.z *= iv0.z * k0; v0.w *= iv0.w * k0;
        v1.x *= iv1.x * k1; v1.y *= iv1.y * k1; v1.z *= iv1.z * k1; v1.w *= iv1.w * k1;
        arow0[j] = v0;
        arow1[j] = v1;
    }
}

// ---------------------------------------------------------------------------
extern "C" void kernel_launch(void* const* d_in, const int* in_sizes, int n_in,
                              void* d_out, int out_size) {
    const float* x      = (const float*)d_in[0];
    const float* W_subj = (const float*)d_in[1];
    const float* b_subj = (const float*)d_in[2];
    const float* W_obj  = (const float*)d_in[3];
    const float* b_obj  = (const float*)d_in[4];
    const float* W_t    = (const float*)d_in[5];
    const float* b_t    = (const float*)d_in[6];
    const int*   mask   = (const int*)d_in[7];

    float* out   = (float*)d_out;
    float* xnew  = out;                          // (B,T,2C)
    float* attn  = out + (size_t)M * C2;         // (B,T,T,HEADS)

    float *subj, *obj, *part, *swow;
    cudaGetSymbolAddress((void**)&subj, g_subj);
    cudaGetSymbolAddress((void**)&obj, g_obj);
    cudaGetSymbolAddress((void**)&part, g_part);
    cudaGetSymbolAddress((void**)&swow, g_swow);

    pool_concat_kernel<<<(M * C2 + 255) / 256, 256>>>(x, xnew);

    dim3 gg(C / 64, M / 64, 2);   // (4, 32, 2) = 256 blocks
    gemm_kernel<<<gg, 256>>>(xnew, W_subj, b_subj, W_obj, b_obj, subj, obj);

    swow_kernel<<<(2 * M) / 4, 128>>>(subj, obj, W_t, swow);

    dim3 ga(T / TJ, T / TI, B);   // (8, 16, 4) = 512 blocks
    rep_exp_kernel<<<ga, 256>>>(subj, obj, W_t, b_t, swow, attn, part);

    normalize_kernel<<<M / 2, 256>>>(part, mask, attn);
}